// round 17
// baseline (speedup 1.0000x reference)
#include <cuda_runtime.h>
#include <cuda_fp16.h>
#include <cstdint>

// ============================================================================
// HQQ grouped int4 GEMM, sm_103 base target.
//
// R17: FUSED single kernel. Grid = 2048 CTAs (e = bid>>8, mt = (bid>>3)&31,
// nt = bid&7):
//   - bid < 512: CTA first dequantizes W slab `bid` (kchunk = bid>>3, expert
//     = bid&7) -> k-ordered production matching consumption order.
//   - nt == 0 : CTA converts its m-tile of x to fp16 (xflag per (e,mt)).
//   - all real CTAs: R16 GEMM (64x256 tile, BK=32, 4-stage cp.async ring,
//     depth-3 prefetch), spinning on wflag[(ch<<3)|e] before each prefetch.
// Flags: __threadfence + st.release / ld.acquire spin; reset via memsetAsync.
// ============================================================================

namespace {

constexpr int kE   = 8;
constexpr int kT   = 2048;
constexpr int kIN  = 2048;
constexpr int kOUT = 2048;
constexpr int kG   = 32;

constexpr int kBM  = 64;
constexpr int kBN  = 256;
constexpr int kBK  = 32;
constexpr int kNCh = kIN / kBK;           // 64
constexpr int kThreads = 256;             // 8 warps, grid 2(m) x 4(n)

constexpr int kARowB  = kBK * 2;          // 64B per m-row
constexpr int kATileB = kBM * kARowB;     // 4 KB
constexpr int kBRowB  = kBN * 2;          // 512B per k-row
constexpr int kBTileB = kBK * kBRowB;     // 16 KB
constexpr int kStageB = kATileB + kBTileB;          // 20480
constexpr int kSmemB  = 4 * kStageB;                // 81920 (x2 CTAs = 160KB)

constexpr int kNSlab  = kE * kNCh;        // 512 W slabs (32k x 2048n each)

__device__ __half g_xh[(size_t)kT * kIN];
__device__ __half g_W[(size_t)kE * kIN * kOUT];     // k-major, same layout as q
__device__ int    g_flags[kNSlab + kE * 32];        // wflags | xflags

// ---------------------------------------------------------------------------

__device__ __forceinline__ uint32_t smem_u32(const void* p) {
  uint32_t a;
  asm("{ .reg .u64 t; cvta.to.shared.u64 t, %1; cvt.u32.u64 %0, t; }" : "=r"(a) : "l"(p));
  return a;
}

__device__ __forceinline__ uint32_t pack_f16x2(float lo, float hi) {
  uint32_t r;
  asm("cvt.rn.f16x2.f32 %0, %1, %2;" : "=r"(r) : "f"(hi), "f"(lo));
  return r;
}

__device__ __forceinline__ void ldsm_x4(uint32_t* r, uint32_t addr) {
  asm volatile("ldmatrix.sync.aligned.m8n8.x4.shared.b16 {%0,%1,%2,%3}, [%4];"
               : "=r"(r[0]), "=r"(r[1]), "=r"(r[2]), "=r"(r[3]) : "r"(addr));
}

__device__ __forceinline__ void ldsm_x4_trans(uint32_t* r, uint32_t addr) {
  asm volatile("ldmatrix.sync.aligned.m8n8.x4.trans.shared.b16 {%0,%1,%2,%3}, [%4];"
               : "=r"(r[0]), "=r"(r[1]), "=r"(r[2]), "=r"(r[3]) : "r"(addr));
}

__device__ __forceinline__ void mma_f16(float* c, const uint32_t* a,
                                        uint32_t b0, uint32_t b1) {
  asm volatile(
      "mma.sync.aligned.m16n8k16.row.col.f32.f16.f16.f32 "
      "{%0,%1,%2,%3}, {%4,%5,%6,%7}, {%8,%9}, {%0,%1,%2,%3};"
      : "+f"(c[0]), "+f"(c[1]), "+f"(c[2]), "+f"(c[3])
      : "r"(a[0]), "r"(a[1]), "r"(a[2]), "r"(a[3]), "r"(b0), "r"(b1));
}

__device__ __forceinline__ void cp16(uint32_t smem_addr, const void* gmem,
                                     uint32_t src_bytes) {
  asm volatile("cp.async.cg.shared.global [%0], [%1], 16, %2;"
               :: "r"(smem_addr), "l"(gmem), "r"(src_bytes) : "memory");
}

#define CP_COMMIT() asm volatile("cp.async.commit_group;" ::: "memory")
#define CP_WAIT2()  asm volatile("cp.async.wait_group 2;" ::: "memory")

__device__ __forceinline__ void set_flag(int* f) {
  asm volatile("st.release.gpu.u32 [%0], %1;" :: "l"(f), "r"(1) : "memory");
}

__device__ __forceinline__ void wait_flag(const int* f) {
  int v;
  asm volatile("ld.acquire.gpu.u32 %0, [%1];" : "=r"(v) : "l"(f) : "memory");
  while (!v) {
    __nanosleep(64);
    asm volatile("ld.acquire.gpu.u32 %0, [%1];" : "=r"(v) : "l"(f) : "memory");
  }
}

// ---------------------------------------------------------------------------

__global__ void __launch_bounds__(kThreads, 2)
hqq_fused_kernel(const float* __restrict__ x,
                 const int* __restrict__ qw,
                 const float* __restrict__ snz,
                 const int* __restrict__ tpe,
                 float* __restrict__ out) {
  extern __shared__ __align__(1024) char smem[];
  const int tid = threadIdx.x;
  const int wid = tid >> 5;
  const int l   = tid & 31;
  const int bid = blockIdx.x;

  const int e  = bid >> 8;
  const int mt = (bid >> 3) & 31;
  const int nt = bid & 7;

  int off = 0, cnt = 0;
#pragma unroll
  for (int i = 0; i < kE; i++) {
    int c = __ldg(&tpe[i]);
    if (i < e) off += c;
    if (i == e) cnt = c;
  }
  const int row0  = off + mt * kBM;
  const int nrows = min(kBM, cnt - mt * kBM);   // may be <= 0 (empty tile)
  const int n0    = nt * kBN;

  // ---- phase 0a: x -> fp16 for this m-tile (nt == 0 CTAs) ----
  if (nt == 0 && nrows > 0) {
    const int segs = nrows * (kIN / 4 / 4) * 4;   // nrows * 512 float4 segs
    for (int i = tid; i < segs; i += kThreads) {
      const int r = i >> 9;
      const int c = (i & 511) * 4;
      const float4 v = *(const float4*)(x + (size_t)(row0 + r) * kIN + c);
      uint2 o;
      o.x = pack_f16x2(v.x, v.y);
      o.y = pack_f16x2(v.z, v.w);
      *(uint2*)(&g_xh[(size_t)(row0 + r) * kIN + c]) = o;
    }
    __threadfence();
    __syncthreads();
    if (tid == 0) set_flag(&g_flags[kNSlab + e * 32 + mt]);
  }

  // ---- phase 0b: dequantize W slab `bid` (first 512 CTAs, k-ordered) ----
  if (bid < kNSlab) {
    const int kc = bid >> 3;                 // kchunk 0..63 (k-ordered!)
    const int ep = bid & 7;                  // producing-for expert
    const int k0 = kc * kBK;
    const int g  = k0 >> 6;
#pragma unroll
    for (int u = 0; u < 8; u++) {
      const int unit = u * 256 + tid;
      const int k8 = unit >> 9;              // 0..3
      const int n  = (unit & 511) * 4;
      const int kk = k0 + k8 * 8;
      const float* sp = snz + (((size_t)ep * kG + g) * kOUT + n) * 2;
      const float4 sa = *(const float4*)(sp);
      const float4 sb = *(const float4*)(sp + 4);
      const float s0 = sa.x, zp0 = fmaf(-8.f, sa.x, sa.y);
      const float s1 = sa.z, zp1 = fmaf(-8.f, sa.z, sa.w);
      const float s2 = sb.x, zp2 = fmaf(-8.f, sb.x, sb.y);
      const float s3 = sb.z, zp3 = fmaf(-8.f, sb.z, sb.w);
#pragma unroll
      for (int j = 0; j < 8; j++) {
        const size_t row = (size_t)ep * kIN + kk + j;
        const int4 q = *(const int4*)(qw + row * kOUT + n);
        uint2 o;
        o.x = pack_f16x2(fmaf((float)q.x, s0, zp0), fmaf((float)q.y, s1, zp1));
        o.y = pack_f16x2(fmaf((float)q.z, s2, zp2), fmaf((float)q.w, s3, zp3));
        *(uint2*)(&g_W[row * kOUT + n]) = o;
      }
    }
    __threadfence();
    __syncthreads();
    if (tid == 0) set_flag(&g_flags[bid]);
  }

  if (nrows <= 0) return;                    // empty m-tile: produced, done

  // ---- GEMM (R16 structure) ----
  const uint32_t sbase = smem_u32(smem);

  const int wm = wid >> 2;
  const int wn = wid & 3;
  const int bj = l & 7;
  const int segA4 = l >> 4;

  uint32_t aRowB[2];
  int aHalf[2];
#pragma unroll
  for (int mi = 0; mi < 2; mi++) {
    const int row = wm * 32 + (l & 15) + mi * 16;
    aRowB[mi] = (uint32_t)(row * kARowB);
    aHalf[mi] = (row >> 1) & 3;
  }

  const int bkoff = ((l >> 3) & 1) * 8 + bj;
  uint32_t bChunk[4];
#pragma unroll
  for (int ni2 = 0; ni2 < 4; ni2++)
    bChunk[ni2] = (uint32_t)(((wn * 8 + ni2 * 2 + (l >> 4)) ^ bj) * 16);

  const __half* xh_base = &g_xh[0];
  const __half* w_base  = &g_W[(size_t)e * kIN * kOUT];

  const int cpAm = tid >> 2, cpAx = tid & 3;
  const uint32_t cpAslot = (uint32_t)(((cpAx + (cpAm >> 1)) & 3) * 16);

  auto issue_stage = [&](int ch, uint32_t st) {
    const int k0 = ch * kBK;
    cp16(st + (uint32_t)(cpAm * kARowB) + cpAslot,
         xh_base + (size_t)(row0 + cpAm) * kIN + k0 + cpAx * 8,
         (cpAm < nrows) ? 16u : 0u);
    const uint32_t stB = st + kATileB;
#pragma unroll
    for (int i = 0; i < 4; i++) {
      const int g = i * 256 + tid;
      const int krow = g >> 5, nchunk = g & 31;
      cp16(stB + (uint32_t)(krow * kBRowB + ((nchunk ^ (krow & 7)) * 16)),
           w_base + (size_t)(k0 + krow) * kOUT + n0 + nchunk * 8, 16u);
    }
    CP_COMMIT();
  };

  float mast[64];
#pragma unroll
  for (int i = 0; i < 64; i++) mast[i] = 0.f;

  auto compute_stage = [&](uint32_t base) {
    const uint32_t baseB = base + kATileB + (uint32_t)(bkoff * kBRowB);
#pragma unroll
    for (int ks = 0; ks < 2; ks++) {
      uint32_t Af[2][4];
      const int xx = ks * 2 + segA4;
#pragma unroll
      for (int mi = 0; mi < 2; mi++)
        ldsm_x4(Af[mi], base + aRowB[mi] +
                         (uint32_t)(((xx + aHalf[mi]) & 3) * 16));
      const uint32_t bK = baseB + (uint32_t)(ks * 16 * kBRowB);
#pragma unroll
      for (int ni2 = 0; ni2 < 4; ni2++) {
        uint32_t r[4];
        ldsm_x4_trans(r, bK + bChunk[ni2]);
#pragma unroll
        for (int mi = 0; mi < 2; mi++) {
          mma_f16(&mast[(mi * 8 + ni2 * 2) * 4],     Af[mi], r[0], r[1]);
          mma_f16(&mast[(mi * 8 + ni2 * 2 + 1) * 4], Af[mi], r[2], r[3]);
        }
      }
    }
  };

  // wait for x (this m-tile) and the first three W slabs of this expert
  if (nt != 0) wait_flag(&g_flags[kNSlab + e * 32 + mt]);
  wait_flag(&g_flags[(0 << 3) | e]);
  wait_flag(&g_flags[(1 << 3) | e]);
  wait_flag(&g_flags[(2 << 3) | e]);

  // ---- 4-stage ring, prefetch depth 3 (wait_group<2>) ----
  issue_stage(0, sbase);
  issue_stage(1, sbase + kStageB);
  issue_stage(2, sbase + 2 * kStageB);

  for (int ch = 0; ch < kNCh; ch++) {
    CP_WAIT2();
    __syncthreads();
    if (ch + 3 < kNCh) {
      wait_flag(&g_flags[((ch + 3) << 3) | e]);
      issue_stage(ch + 3, sbase + ((ch + 3) & 3) * kStageB);
    } else {
      CP_COMMIT();
    }
    compute_stage(sbase + (ch & 3) * kStageB);
  }

  // ---- epilogue ----
#pragma unroll
  for (int mi = 0; mi < 2; mi++) {
#pragma unroll
    for (int ni = 0; ni < 8; ni++) {
      const float* c = &mast[(mi * 8 + ni) * 4];
      const int r0  = wm * 32 + mi * 16 + (l >> 2);
      const int col = n0 + wn * 64 + ni * 8 + (l & 3) * 2;
      if (r0 < nrows)
        *(float2*)(out + (size_t)(row0 + r0) * kOUT + col) = make_float2(c[0], c[1]);
      if (r0 + 8 < nrows)
        *(float2*)(out + (size_t)(row0 + r0 + 8) * kOUT + col) = make_float2(c[2], c[3]);
    }
  }
}

}  // namespace

// ---------------------------------------------------------------------------

extern "C" void kernel_launch(void* const* d_in, const int* in_sizes, int n_in,
                              void* d_out, int out_size) {
  (void)in_sizes; (void)n_in; (void)out_size;
  const float* x   = (const float*)d_in[0];
  const int*   qw  = (const int*)d_in[1];
  const float* snz = (const float*)d_in[2];
  const int*   tpe = (const int*)d_in[3];
  float* out = (float*)d_out;

  (void)cudaFuncSetAttribute(hqq_fused_kernel,
                             cudaFuncAttributeMaxDynamicSharedMemorySize, kSmemB);

  void* flags_ptr = nullptr;
  (void)cudaGetSymbolAddress(&flags_ptr, g_flags);
  (void)cudaMemsetAsync(flags_ptr, 0, sizeof(int) * (kNSlab + kE * 32));

  hqq_fused_kernel<<<kE * 32 * 8, kThreads, kSmemB>>>(x, qw, snz, tpe, out);
}